// round 12
// baseline (speedup 1.0000x reference)
#include <cuda_runtime.h>
#include <cuda_fp16.h>
#include <cstdint>

#define N_NODES 32
#define DIM 96
#define N_EDGES 256
#define PPAIR 1024
#define M_TOT (PPAIR * N_EDGES)   // 262144 samples

// ---------------- scratch (static device globals; no allocation) ----------------
__device__ uint32_t g_feath[M_TOT * 8];  // conv features, half2 words [sample][8]
__device__ float g_preds[M_TOT];         // preds row-major: [p * 256 + e]
__device__ float g_part[128 * 32];       // prop per-block rbc partials
__device__ float g_tab[2 * 6016];        // conv1 tables
// weights pre-packed in m16n8k16 B-fragment half2 order
__device__ uint2 g_w1h[16 * 32];         // [nt][lane]        (K16  N128)
__device__ uint2 g_w2h[8 * 32 * 32];     // [kt][nt][lane]    (K128 N256)
__device__ uint2 g_w3h[16 * 16 * 32];    // [kt][nt][lane]    (K256 N128)

// ---------------- helpers ----------------
__device__ __forceinline__ uint32_t packh2(float a, float b) {
    __half2 h = __floats2half2_rn(a, b);
    return *(uint32_t*)&h;
}
__device__ __forceinline__ void mma_f16(float c[4], const uint32_t a[4],
                                        uint32_t b0, uint32_t b1) {
    asm("mma.sync.aligned.m16n8k16.row.col.f32.f16.f16.f32 "
        "{%0,%1,%2,%3}, {%4,%5,%6,%7}, {%8,%9}, {%0,%1,%2,%3};"
        : "+f"(c[0]), "+f"(c[1]), "+f"(c[2]), "+f"(c[3])
        : "r"(a[0]), "r"(a[1]), "r"(a[2]), "r"(a[3]), "r"(b0), "r"(b1));
}
__device__ __forceinline__ void ldmatrix_x4(uint32_t a[4], uint32_t addr) {
    asm volatile("ldmatrix.sync.aligned.m8n8.x4.shared.b16 {%0,%1,%2,%3}, [%4];"
        : "=r"(a[0]), "=r"(a[1]), "=r"(a[2]), "=r"(a[3]) : "r"(addr));
}

// =======================================================================
// Kernel 0a: pack FC weights into m16n8k16 B-fragment half2 order.
// =======================================================================
__global__ void prep_weights(const float* __restrict__ fc1w,
                             const float* __restrict__ fc2w,
                             const float* __restrict__ fc3w)
{
    int i = blockIdx.x * 256 + threadIdx.x;   // 32 blocks -> [0, 8192)
    int ln = i & 31;
    {   // W2: KT=8 (K128), NT=32 (N256)
        int nt = (i >> 5) & 31, kt = i >> 10;
        int k0 = 16 * kt + (ln & 3) * 2, n = 8 * nt + (ln >> 2);
        uint2 v;
        v.x = packh2(fc2w[k0 * 256 + n], fc2w[(k0 + 1) * 256 + n]);
        v.y = packh2(fc2w[(k0 + 8) * 256 + n], fc2w[(k0 + 9) * 256 + n]);
        g_w2h[i] = v;
    }
    {   // W3: KT=16 (K256), NT=16 (N128)
        int nt = (i >> 5) & 15, kt = i >> 9;
        int k0 = 16 * kt + (ln & 3) * 2, n = 8 * nt + (ln >> 2);
        uint2 v;
        v.x = packh2(fc3w[k0 * 128 + n], fc3w[(k0 + 1) * 128 + n]);
        v.y = packh2(fc3w[(k0 + 8) * 128 + n], fc3w[(k0 + 9) * 128 + n]);
        g_w3h[i] = v;
    }
    if (i < 512) {    // W1: KT=1 (K16), NT=16 (N128)
        int nt = i >> 5;
        int k0 = (ln & 3) * 2, n = 8 * nt + (ln >> 2);
        uint2 v;
        v.x = packh2(fc1w[k0 * 128 + n], fc1w[(k0 + 1) * 128 + n]);
        v.y = packh2(fc1w[(k0 + 8) * 128 + n], fc1w[(k0 + 9) * 128 + n]);
        g_w1h[i] = v;
    }
}

// =======================================================================
// Kernel 0b: conv1 channel tables for roles u (ch2) and v (ch3).
// =======================================================================
__global__ void prep_tab(const float* __restrict__ emb, const float* __restrict__ w1)
{
    int i = blockIdx.x * 256 + threadIdx.x;   // 47 blocks -> [0, 12032)
    if (i >= 12032) return;
    int role = (i >= 6016) ? 1 : 0;
    int rem = i - role * 6016;
    int o = rem / 1504;
    int pos = (rem >> 5) % 47;
    int node = rem & 31;
    int ch = 2 + role;
    float acc = 0.f;
#pragma unroll
    for (int k = 0; k < 3; k++)
        acc += w1[o * 12 + ch * 3 + k] * emb[node * DIM + 2 * pos + k];
    g_tab[i] = acc;
}

// =======================================================================
// Kernel 1: conv stack. Block = one p (s,t fixed), 256 threads = 256 e.
// =======================================================================
__global__ void __launch_bounds__(256) conv_kernel(
    const float* __restrict__ emb, const int* __restrict__ edges,
    const float* __restrict__ w1, const float* __restrict__ b1,
    const float* __restrict__ w2, const float* __restrict__ b2,
    const float* __restrict__ w3, const float* __restrict__ b3)
{
    __shared__ float stab[2 * 6016];     // 48KB
    __shared__ float ssum[188];
    __shared__ int   sedge[N_EDGES * 2];
    __shared__ float sw2[48], sb2_[4], sw3[48], sb3_[4];
    __shared__ float sfeat[256][17];

    int tid = threadIdx.x;
    int p = blockIdx.x;
    int s = p >> 5, t = p & 31;

    for (int i = tid; i < 12032; i += 256) stab[i] = g_tab[i];
    for (int i = tid; i < N_EDGES * 2; i += 256) sedge[i] = edges[i];
    if (tid < 48) { sw2[tid] = w2[tid]; sw3[tid] = w3[tid]; }
    if (tid < 4)  { sb2_[tid] = b2[tid]; sb3_[tid] = b3[tid]; }
    if (tid < 188) {
        int o = tid / 47, pos = tid % 47;
        float acc = b1[o];
#pragma unroll
        for (int k = 0; k < 3; k++) {
            acc += w1[o * 12 + 0 * 3 + k] * emb[s * DIM + 2 * pos + k];
            acc += w1[o * 12 + 1 * 3 + k] * emb[t * DIM + 2 * pos + k];
        }
        ssum[tid] = acc;
    }
    __syncthreads();

    int e = tid;
    int uoff = sedge[2 * e];
    int voff = 6016 + sedge[2 * e + 1];

#pragma unroll
    for (int m = 0; m < 4; m++) {
        float h1c[4][10];
#pragma unroll
        for (int c = 0; c < 10; c++) {
            int j = 4 * m + c;
            int q0 = 2 * j, q1 = 2 * j + 1;
#pragma unroll
            for (int o = 0; o < 4; o++) {
                int i0 = o * 47 + q0, i1 = o * 47 + q1;
                float v0 = ssum[i0] + stab[uoff + i0 * 32] + stab[voff + i0 * 32];
                float v1 = ssum[i1] + stab[uoff + i1 * 32] + stab[voff + i1 * 32];
                h1c[o][c] = fmaxf(fmaxf(v0, v1), 0.f);
            }
        }
        float h2c[4][4];
#pragma unroll
        for (int c = 0; c < 4; c++) {
#pragma unroll
            for (int o = 0; o < 4; o++) {
                float y0 = sb2_[o], y1 = sb2_[o];
#pragma unroll
                for (int i = 0; i < 4; i++)
#pragma unroll
                    for (int k = 0; k < 3; k++) {
                        float w = sw2[o * 12 + i * 3 + k];
                        y0 += w * h1c[i][2 * c + k];
                        y1 += w * h1c[i][2 * c + 1 + k];
                    }
                h2c[o][c] = fmaxf(fmaxf(y0, y1), 0.f);
            }
        }
#pragma unroll
        for (int o = 0; o < 4; o++) {
            float y0 = sb3_[o], y1 = sb3_[o];
#pragma unroll
            for (int i = 0; i < 4; i++)
#pragma unroll
                for (int k = 0; k < 3; k++) {
                    float w = sw3[o * 12 + i * 3 + k];
                    y0 += w * h2c[i][k];
                    y1 += w * h2c[i][k + 1];
                }
            sfeat[tid][o * 4 + m] = fmaxf(fmaxf(y0, y1), 0.f);
        }
    }
    __syncthreads();
#pragma unroll
    for (int ii = 0; ii < 8; ii++) {
        int idx = tid + ii * 256;        // 0..2047
        int l2 = idx >> 3, wc = idx & 7;
        g_feath[blockIdx.x * 2048 + idx] =
            packh2(sfeat[l2][2 * wc], sfeat[l2][2 * wc + 1]);
    }
}

// =======================================================================
// Kernel 2: fused FC stack, fp16 m16n8k16. M128/block, 8 warps x M16,
// 2 blocks/SM (occupancy fix). ldmatrix.x4 A-fragment loads; activation
// word strides 68 / 20 (== 4 mod 8) keep ldmatrix conflict-free.
// =======================================================================
#define SH1   0                    // [128][68 words] H1 half2
#define SH1S  68
#define SH2   8704                 // [128][20 words] H2 chunk half2
#define SH2S  20
#define SB2   11264                // 1024 uint2 W2 chunk frags
#define SB3   13312                // 1024 uint2 W3 chunk frags
#define SW1F  15360                // 512 uint2 W1 frags
#define SBIAS 16384                // f32: b1(128) b2(256) b3(128) w4(128) b4(1)
#define FC_SMEM_WORDS 17025
#define FC_SMEM_BYTES (FC_SMEM_WORDS * 4)

__global__ void __launch_bounds__(256, 2) fc_mma_kernel(
    const float* __restrict__ fc1b, const float* __restrict__ fc2b,
    const float* __restrict__ fc3b, const float* __restrict__ fc4w,
    const float* __restrict__ fc4b)
{
    extern __shared__ uint32_t smw[];
    uint32_t* sH1w = smw + SH1;
    uint32_t* sH2w = smw + SH2;
    uint2* b2f = (uint2*)(smw + SB2);
    uint2* b3f = (uint2*)(smw + SB3);
    uint2* w1f = (uint2*)(smw + SW1F);
    float* sb  = (float*)(smw + SBIAS);
    uint32_t smem_u32 = (uint32_t)__cvta_generic_to_shared(smw);

    int tid = threadIdx.x, wid = tid >> 5, lane = tid & 31;
    int r = lane >> 2, cc = lane & 3;
    int m0 = blockIdx.x * 128;
    int mb = wid * 16;

    for (int i = tid; i < 512; i += 256) w1f[i] = g_w1h[i];
    for (int i = tid; i < 641; i += 256) {
        float v;
        if (i < 128)      v = fc1b[i];
        else if (i < 384) v = fc2b[i - 128];
        else if (i < 512) v = fc3b[i - 384];
        else if (i < 640) v = fc4w[i - 512];
        else              v = fc4b[0];
        sb[i] = v;
    }
    __syncthreads();

    // per-lane ldmatrix base addresses (row = mb + lane%16, k-half = lane/16)
    uint32_t lmrow = (uint32_t)(mb + (lane & 15));
    uint32_t lmk   = (uint32_t)((lane >> 4) << 2);   // +4 words = +8 halves
    uint32_t h1la  = smem_u32 + (SH1 + lmrow * SH1S + lmk) * 4;
    uint32_t h2la  = smem_u32 + (SH2 + lmrow * SH2S + lmk) * 4;

    // ---- fc1: H1[128][128] = relu(F @ W1 + b1)  (K=16, 1 k-step) ----
    {
        float C1[16][4];
#pragma unroll
        for (int nt = 0; nt < 16; nt++)
#pragma unroll
            for (int q = 0; q < 4; q++) C1[nt][q] = 0.f;

        uint32_t a[4];
        {
            int base = (m0 + mb) * 8;
            a[0] = g_feath[base + r * 8 + cc];
            a[1] = g_feath[base + (r + 8) * 8 + cc];
            a[2] = g_feath[base + r * 8 + cc + 4];
            a[3] = g_feath[base + (r + 8) * 8 + cc + 4];
        }
#pragma unroll
        for (int nt = 0; nt < 16; nt++) {
            uint2 bf = w1f[nt * 32 + lane];
            mma_f16(C1[nt], a, bf.x, bf.y);
        }
#pragma unroll
        for (int nt = 0; nt < 16; nt++) {
            int col = 8 * nt + 2 * cc;
            float b0 = sb[col], b1 = sb[col + 1];
            int row = mb + r;
            sH1w[row * SH1S + 4 * nt + cc] =
                packh2(fmaxf(C1[nt][0] + b0, 0.f), fmaxf(C1[nt][1] + b1, 0.f));
            sH1w[(row + 8) * SH1S + 4 * nt + cc] =
                packh2(fmaxf(C1[nt][2] + b0, 0.f), fmaxf(C1[nt][3] + b1, 0.f));
        }
        __syncwarp();
    }

    // ---- fc2 + fc3, 8 chunks of N2=32 (fc3 accumulates over K=256) ----
    float C3[16][4];
#pragma unroll
    for (int nt = 0; nt < 16; nt++)
#pragma unroll
        for (int q = 0; q < 4; q++) C3[nt][q] = 0.f;

    for (int nc = 0; nc < 8; nc++) {
        __syncthreads();   // prior chunk's B reads complete
#pragma unroll
        for (int ii = 0; ii < 4; ii++) {
            int i = tid + ii * 256;
            int ln = i & 31, ntl = (i >> 5) & 3, kt = i >> 7;
            b2f[i] = g_w2h[(kt * 32 + nc * 4 + ntl) * 32 + ln];
        }
#pragma unroll
        for (int ii = 0; ii < 4; ii++) {
            int i = tid + ii * 256;
            int ln = i & 31, nt = (i >> 5) & 15, ktl = i >> 9;
            b3f[i] = g_w3h[((nc * 2 + ktl) * 16 + nt) * 32 + ln];
        }
        __syncthreads();

        // fc2: H2chunk[128][32] = relu(H1 @ W2[:, nc*32:+32] + b2)
        float C2[4][4];
#pragma unroll
        for (int nt = 0; nt < 4; nt++)
#pragma unroll
            for (int q = 0; q < 4; q++) C2[nt][q] = 0.f;

#pragma unroll
        for (int kt = 0; kt < 8; kt++) {
            uint32_t a[4];
            ldmatrix_x4(a, h1la + kt * 32);
#pragma unroll
            for (int ntl = 0; ntl < 4; ntl++) {
                uint2 bf = b2f[(kt * 4 + ntl) * 32 + lane];
                mma_f16(C2[ntl], a, bf.x, bf.y);
            }
        }
#pragma unroll
        for (int ntl = 0; ntl < 4; ntl++) {
            int col = 8 * ntl + 2 * cc;
            float b0 = sb[128 + nc * 32 + col];
            float b1 = sb[128 + nc * 32 + col + 1];
            int row = mb + r;
            sH2w[row * SH2S + 4 * ntl + cc] =
                packh2(fmaxf(C2[ntl][0] + b0, 0.f), fmaxf(C2[ntl][1] + b1, 0.f));
            sH2w[(row + 8) * SH2S + 4 * ntl + cc] =
                packh2(fmaxf(C2[ntl][2] + b0, 0.f), fmaxf(C2[ntl][3] + b1, 0.f));
        }
        __syncwarp();

        // fc3: C3 += H2chunk @ W3[nc*32:+32, :]
#pragma unroll
        for (int ktl = 0; ktl < 2; ktl++) {
            uint32_t a[4];
            ldmatrix_x4(a, h2la + ktl * 32);
#pragma unroll
            for (int nt = 0; nt < 16; nt++) {
                uint2 bf = b3f[(ktl * 16 + nt) * 32 + lane];
                mma_f16(C3[nt], a, bf.x, bf.y);
            }
        }
    }

    // ---- fc4: pred = relu(C3 + b3) . w4 + b4; reduce over 4 cc-lanes ----
    float bias4 = sb[640];
    {
        float acc0 = 0.f, acc1 = 0.f;
#pragma unroll
        for (int nt = 0; nt < 16; nt++) {
            int col = 8 * nt + 2 * cc;
            float b30 = sb[384 + col], b31 = sb[384 + col + 1];
            float w40 = sb[512 + col], w41 = sb[512 + col + 1];
            acc0 += fmaxf(C3[nt][0] + b30, 0.f) * w40
                  + fmaxf(C3[nt][1] + b31, 0.f) * w41;
            acc1 += fmaxf(C3[nt][2] + b30, 0.f) * w40
                  + fmaxf(C3[nt][3] + b31, 0.f) * w41;
        }
        acc0 += __shfl_xor_sync(0xffffffffu, acc0, 1);
        acc0 += __shfl_xor_sync(0xffffffffu, acc0, 2);
        acc1 += __shfl_xor_sync(0xffffffffu, acc1, 1);
        acc1 += __shfl_xor_sync(0xffffffffu, acc1, 2);
        if (cc == 0) {
            int g0 = m0 + mb + r;
#pragma unroll
            for (int h = 0; h < 2; h++) {
                int gidx = g0 + h * 8;
                float pred = (h == 0 ? acc0 : acc1) + bias4;
                int p = gidx >> 8;
                if ((p >> 5) == (p & 31)) pred = 0.f;   // s == t mask
                g_preds[gidx] = pred;
            }
        }
    }
}

// =======================================================================
// Kernel 3: propagation — warp per row p; block partials to g_part.
// =======================================================================
#define PW 8
__global__ void __launch_bounds__(PW * 32) prop_kernel(const int* __restrict__ edges)
{
    __shared__ float spart[PW][32 * 33];
    __shared__ float srbc[N_NODES];
    __shared__ int sue[N_EDGES], sve[N_EDGES];

    int tid = threadIdx.x, l = tid & 31, w = tid >> 5;
    if (tid < 32) srbc[tid] = 0.f;
    for (int i = tid; i < N_EDGES; i += PW * 32) {
        sue[i] = edges[2 * i];
        sve[i] = edges[2 * i + 1];
    }
    __syncthreads();

    int p = blockIdx.x * PW + w;
    int s = p >> 5;

    int eu[8], ev[8];
    float pr[8];
#pragma unroll
    for (int k = 0; k < 8; k++) { eu[k] = sue[l * 8 + k]; ev[k] = sve[l * 8 + k]; }
    {
        float4 p0 = *(const float4*)&g_preds[p * 256 + l * 8];
        float4 p1 = *(const float4*)&g_preds[p * 256 + l * 8 + 4];
        pr[0] = p0.x; pr[1] = p0.y; pr[2] = p0.z; pr[3] = p0.w;
        pr[4] = p1.x; pr[5] = p1.y; pr[6] = p1.z; pr[7] = p1.w;
    }

    float x = (l == s) ? 1.f : 0.f;
    float racc = 0.f;
    float* part = spart[w];

    for (int step = 0; step < 3; step++) {
#pragma unroll
        for (int j = 0; j < 32; j++) part[l * 33 + j] = 0.f;
        __syncwarp();
#pragma unroll
        for (int k = 0; k < 8; k++) {
            float xv = __shfl_sync(0xffffffffu, x, eu[k]);
            part[l * 33 + ev[k]] += xv * pr[k];
        }
        __syncwarp();
        float xn = 0.f;
#pragma unroll
        for (int i = 0; i < 32; i++) xn += part[i * 33 + l];
        x = xn;
        racc += xn;
        __syncwarp();
    }

    atomicAdd(&srbc[l], racc);
    __syncthreads();
    if (tid < 32) g_part[blockIdx.x * 32 + tid] = srbc[tid];
}

__global__ void norm_kernel(float* __restrict__ out) {
    int l = threadIdx.x;   // 32 lanes
    float v = 0.f;
#pragma unroll 8
    for (int b = 0; b < 128; b++) v += g_part[b * 32 + l];
    float sum = v;
#pragma unroll
    for (int o = 16; o > 0; o >>= 1) sum += __shfl_xor_sync(0xffffffffu, sum, o);
    out[l] = v / sum;
}

// =======================================================================
extern "C" void kernel_launch(void* const* d_in, const int* in_sizes, int n_in,
                              void* d_out, int out_size)
{
    const float* emb  = (const float*)d_in[0];
    const int*   edges= (const int*)  d_in[1];
    const float* w1   = (const float*)d_in[2];
    const float* b1   = (const float*)d_in[3];
    const float* w2   = (const float*)d_in[4];
    const float* b2   = (const float*)d_in[5];
    const float* w3   = (const float*)d_in[6];
    const float* b3   = (const float*)d_in[7];
    const float* fc1w = (const float*)d_in[8];
    const float* fc1b = (const float*)d_in[9];
    const float* fc2w = (const float*)d_in[10];
    const float* fc2b = (const float*)d_in[11];
    const float* fc3w = (const float*)d_in[12];
    const float* fc3b = (const float*)d_in[13];
    const float* fc4w = (const float*)d_in[14];
    const float* fc4b = (const float*)d_in[15];
    float* out = (float*)d_out;

    cudaFuncSetAttribute(fc_mma_kernel, cudaFuncAttributeMaxDynamicSharedMemorySize,
                         FC_SMEM_BYTES);

    prep_weights<<<32, 256>>>(fc1w, fc2w, fc3w);
    prep_tab<<<47, 256>>>(emb, w1);
    conv_kernel<<<PPAIR, 256>>>(emb, edges, w1, b1, w2, b2, w3, b3);
    fc_mma_kernel<<<M_TOT / 128, 256, FC_SMEM_BYTES>>>(fc1b, fc2b, fc3b, fc4w, fc4b);
    prop_kernel<<<PPAIR / PW, PW * 32>>>(edges);
    norm_kernel<<<1, 32>>>(out);
}

// round 14
// speedup vs baseline: 1.6893x; 1.6893x over previous
#include <cuda_runtime.h>
#include <cuda_fp16.h>
#include <cstdint>

#define N_NODES 32
#define DIM 96
#define N_EDGES 256
#define PPAIR 1024
#define M_TOT (PPAIR * N_EDGES)   // 262144 samples

// ---------------- scratch (static device globals; no allocation) ----------------
__device__ uint32_t g_feath[M_TOT * 8];  // conv features, half2 words [sample][8]
__device__ float g_preds[M_TOT];         // preds row-major: [p * 256 + e]
__device__ float g_part[128 * 32];       // prop per-block rbc partials
__device__ float g_tab[2 * 6016];        // conv1 tables
// weights pre-packed in m16n8k16 B-fragment half2 order
__device__ uint2 g_w1h[16 * 32];         // [nt][lane]        (K16  N128)
__device__ uint2 g_w2h[8 * 32 * 32];     // [kt][nt][lane]    (K128 N256)
__device__ uint2 g_w3h[16 * 16 * 32];    // [kt][nt][lane]    (K256 N128)

// ---------------- helpers ----------------
__device__ __forceinline__ uint32_t packh2(float a, float b) {
    __half2 h = __floats2half2_rn(a, b);
    return *(uint32_t*)&h;
}
__device__ __forceinline__ void mma_f16(float c[4], const uint32_t a[4],
                                        uint32_t b0, uint32_t b1) {
    asm("mma.sync.aligned.m16n8k16.row.col.f32.f16.f16.f32 "
        "{%0,%1,%2,%3}, {%4,%5,%6,%7}, {%8,%9}, {%0,%1,%2,%3};"
        : "+f"(c[0]), "+f"(c[1]), "+f"(c[2]), "+f"(c[3])
        : "r"(a[0]), "r"(a[1]), "r"(a[2]), "r"(a[3]), "r"(b0), "r"(b1));
}
__device__ __forceinline__ void ldmatrix_x4(uint32_t a[4], uint32_t addr) {
    asm volatile("ldmatrix.sync.aligned.m8n8.x4.shared.b16 {%0,%1,%2,%3}, [%4];"
        : "=r"(a[0]), "=r"(a[1]), "=r"(a[2]), "=r"(a[3]) : "r"(addr));
}

// =======================================================================
// Kernel 0a: pack FC weights into m16n8k16 B-fragment half2 order.
// =======================================================================
__global__ void prep_weights(const float* __restrict__ fc1w,
                             const float* __restrict__ fc2w,
                             const float* __restrict__ fc3w)
{
    int i = blockIdx.x * 256 + threadIdx.x;   // 32 blocks -> [0, 8192)
    int ln = i & 31;
    {   // W2: KT=8 (K128), NT=32 (N256)
        int nt = (i >> 5) & 31, kt = i >> 10;
        int k0 = 16 * kt + (ln & 3) * 2, n = 8 * nt + (ln >> 2);
        uint2 v;
        v.x = packh2(fc2w[k0 * 256 + n], fc2w[(k0 + 1) * 256 + n]);
        v.y = packh2(fc2w[(k0 + 8) * 256 + n], fc2w[(k0 + 9) * 256 + n]);
        g_w2h[i] = v;
    }
    {   // W3: KT=16 (K256), NT=16 (N128)
        int nt = (i >> 5) & 15, kt = i >> 9;
        int k0 = 16 * kt + (ln & 3) * 2, n = 8 * nt + (ln >> 2);
        uint2 v;
        v.x = packh2(fc3w[k0 * 128 + n], fc3w[(k0 + 1) * 128 + n]);
        v.y = packh2(fc3w[(k0 + 8) * 128 + n], fc3w[(k0 + 9) * 128 + n]);
        g_w3h[i] = v;
    }
    if (i < 512) {    // W1: KT=1 (K16), NT=16 (N128)
        int nt = i >> 5;
        int k0 = (ln & 3) * 2, n = 8 * nt + (ln >> 2);
        uint2 v;
        v.x = packh2(fc1w[k0 * 128 + n], fc1w[(k0 + 1) * 128 + n]);
        v.y = packh2(fc1w[(k0 + 8) * 128 + n], fc1w[(k0 + 9) * 128 + n]);
        g_w1h[i] = v;
    }
}

// =======================================================================
// Kernel 0b: conv1 channel tables for roles u (ch2) and v (ch3).
// =======================================================================
__global__ void prep_tab(const float* __restrict__ emb, const float* __restrict__ w1)
{
    int i = blockIdx.x * 256 + threadIdx.x;   // 47 blocks -> [0, 12032)
    if (i >= 12032) return;
    int role = (i >= 6016) ? 1 : 0;
    int rem = i - role * 6016;
    int o = rem / 1504;
    int pos = (rem >> 5) % 47;
    int node = rem & 31;
    int ch = 2 + role;
    float acc = 0.f;
#pragma unroll
    for (int k = 0; k < 3; k++)
        acc += w1[o * 12 + ch * 3 + k] * emb[node * DIM + 2 * pos + k];
    g_tab[i] = acc;
}

// =======================================================================
// Kernel 1: conv stack. Block = one p (s,t fixed), 256 threads = 256 e.
// =======================================================================
__global__ void __launch_bounds__(256) conv_kernel(
    const float* __restrict__ emb, const int* __restrict__ edges,
    const float* __restrict__ w1, const float* __restrict__ b1,
    const float* __restrict__ w2, const float* __restrict__ b2,
    const float* __restrict__ w3, const float* __restrict__ b3)
{
    __shared__ float stab[2 * 6016];     // 48KB
    __shared__ float ssum[188];
    __shared__ int   sedge[N_EDGES * 2];
    __shared__ float sw2[48], sb2_[4], sw3[48], sb3_[4];
    __shared__ float sfeat[256][17];

    int tid = threadIdx.x;
    int p = blockIdx.x;
    int s = p >> 5, t = p & 31;

    for (int i = tid; i < 12032; i += 256) stab[i] = g_tab[i];
    for (int i = tid; i < N_EDGES * 2; i += 256) sedge[i] = edges[i];
    if (tid < 48) { sw2[tid] = w2[tid]; sw3[tid] = w3[tid]; }
    if (tid < 4)  { sb2_[tid] = b2[tid]; sb3_[tid] = b3[tid]; }
    if (tid < 188) {
        int o = tid / 47, pos = tid % 47;
        float acc = b1[o];
#pragma unroll
        for (int k = 0; k < 3; k++) {
            acc += w1[o * 12 + 0 * 3 + k] * emb[s * DIM + 2 * pos + k];
            acc += w1[o * 12 + 1 * 3 + k] * emb[t * DIM + 2 * pos + k];
        }
        ssum[tid] = acc;
    }
    __syncthreads();

    int e = tid;
    int uoff = sedge[2 * e];
    int voff = 6016 + sedge[2 * e + 1];

#pragma unroll
    for (int m = 0; m < 4; m++) {
        float h1c[4][10];
#pragma unroll
        for (int c = 0; c < 10; c++) {
            int j = 4 * m + c;
            int q0 = 2 * j, q1 = 2 * j + 1;
#pragma unroll
            for (int o = 0; o < 4; o++) {
                int i0 = o * 47 + q0, i1 = o * 47 + q1;
                float v0 = ssum[i0] + stab[uoff + i0 * 32] + stab[voff + i0 * 32];
                float v1 = ssum[i1] + stab[uoff + i1 * 32] + stab[voff + i1 * 32];
                h1c[o][c] = fmaxf(fmaxf(v0, v1), 0.f);
            }
        }
        float h2c[4][4];
#pragma unroll
        for (int c = 0; c < 4; c++) {
#pragma unroll
            for (int o = 0; o < 4; o++) {
                float y0 = sb2_[o], y1 = sb2_[o];
#pragma unroll
                for (int i = 0; i < 4; i++)
#pragma unroll
                    for (int k = 0; k < 3; k++) {
                        float w = sw2[o * 12 + i * 3 + k];
                        y0 += w * h1c[i][2 * c + k];
                        y1 += w * h1c[i][2 * c + 1 + k];
                    }
                h2c[o][c] = fmaxf(fmaxf(y0, y1), 0.f);
            }
        }
#pragma unroll
        for (int o = 0; o < 4; o++) {
            float y0 = sb3_[o], y1 = sb3_[o];
#pragma unroll
            for (int i = 0; i < 4; i++)
#pragma unroll
                for (int k = 0; k < 3; k++) {
                    float w = sw3[o * 12 + i * 3 + k];
                    y0 += w * h2c[i][k];
                    y1 += w * h2c[i][k + 1];
                }
            sfeat[tid][o * 4 + m] = fmaxf(fmaxf(y0, y1), 0.f);
        }
    }
    __syncthreads();
#pragma unroll
    for (int ii = 0; ii < 8; ii++) {
        int idx = tid + ii * 256;        // 0..2047
        int l2 = idx >> 3, wc = idx & 7;
        g_feath[blockIdx.x * 2048 + idx] =
            packh2(sfeat[l2][2 * wc], sfeat[l2][2 * wc + 1]);
    }
}

// =======================================================================
// Kernel 2: fused FC stack, fp16 m16n8k16. M128/block, 8 warps as 4 pairs
// (g = wid/2 owns M32, h = wid&1 owns an N-half). Warp tiles: fc2 M32xN32,
// fc3 M32xN64 -> B frags reused x2, smem bytes/MMA 328 -> ~219.
// Chunks: 4 x N64. 2 blocks/SM. Strides 68/36 words (==4 mod 8) keep
// ldmatrix + epilogue stores conflict-free.
// =======================================================================
#define SH1   0                    // [128][68 words] H1 half2
#define SH1S  68
#define SH2   8704                 // [128][36 words] H2 chunk half2 (64 cols)
#define SH2S  36
#define SB2   13312                // 2048 uint2 W2 chunk frags (K128 x N64)
#define SB3   17408                // 2048 uint2 W3 chunk frags (K64 x N128)
#define SW1F  21504                // 512 uint2 W1 frags
#define SBIAS 22528                // f32: b1(128) b2(256) b3(128) w4(128) b4(1)
#define SPRED 23172                // f32 [128][2] fc4 pair partials
#define FC_SMEM_WORDS 23432
#define FC_SMEM_BYTES (FC_SMEM_WORDS * 4)

__global__ void __launch_bounds__(256, 2) fc_mma_kernel(
    const float* __restrict__ fc1b, const float* __restrict__ fc2b,
    const float* __restrict__ fc3b, const float* __restrict__ fc4w,
    const float* __restrict__ fc4b)
{
    extern __shared__ uint32_t smw[];
    uint32_t* sH1w = smw + SH1;
    uint32_t* sH2w = smw + SH2;
    uint2* b2f = (uint2*)(smw + SB2);
    uint2* b3f = (uint2*)(smw + SB3);
    uint2* w1f = (uint2*)(smw + SW1F);
    float* sb    = (float*)(smw + SBIAS);
    float* spred = (float*)(smw + SPRED);
    uint32_t smem_u32 = (uint32_t)__cvta_generic_to_shared(smw);

    int tid = threadIdx.x, wid = tid >> 5, lane = tid & 31;
    int r = lane >> 2, cc = lane & 3;
    int g = wid >> 1, h = wid & 1;
    int m0 = blockIdx.x * 128;
    int mb = g * 32;

    for (int i = tid; i < 512; i += 256) w1f[i] = g_w1h[i];
    for (int i = tid; i < 641; i += 256) {
        float v;
        if (i < 128)      v = fc1b[i];
        else if (i < 384) v = fc2b[i - 128];
        else if (i < 512) v = fc3b[i - 384];
        else if (i < 640) v = fc4w[i - 512];
        else              v = fc4b[0];
        sb[i] = v;
    }

    // per-lane ldmatrix base addresses (mt-tile 0; mt=1 adds 16 rows)
    uint32_t lrow = (uint32_t)(mb + (lane & 15));
    uint32_t lkh  = (uint32_t)((lane >> 4) << 2);   // +4 words = +8 halves
    uint32_t h1la0 = smem_u32 + (SH1 + lrow * SH1S + lkh) * 4;
    uint32_t h1la1 = h1la0 + 16 * SH1S * 4;
    uint32_t h2la0 = smem_u32 + (SH2 + lrow * SH2S + lkh) * 4;
    uint32_t h2la1 = h2la0 + 16 * SH2S * 4;

    __syncthreads();

    // ---- fc1: H1[128][128] = relu(F @ W1 + b1); warp: M32 x N64 (h-half) ----
    {
        float C1[2][8][4];
#pragma unroll
        for (int mt = 0; mt < 2; mt++)
#pragma unroll
            for (int nt = 0; nt < 8; nt++)
#pragma unroll
                for (int q = 0; q < 4; q++) C1[mt][nt][q] = 0.f;

        uint32_t a[2][4];
#pragma unroll
        for (int mt = 0; mt < 2; mt++) {
            int base = (m0 + mb + 16 * mt) * 8;
            a[mt][0] = g_feath[base + r * 8 + cc];
            a[mt][1] = g_feath[base + (r + 8) * 8 + cc];
            a[mt][2] = g_feath[base + r * 8 + cc + 4];
            a[mt][3] = g_feath[base + (r + 8) * 8 + cc + 4];
        }
#pragma unroll
        for (int nt = 0; nt < 8; nt++) {
            uint2 bf = w1f[(h * 8 + nt) * 32 + lane];
            mma_f16(C1[0][nt], a[0], bf.x, bf.y);
            mma_f16(C1[1][nt], a[1], bf.x, bf.y);
        }
#pragma unroll
        for (int mt = 0; mt < 2; mt++)
#pragma unroll
            for (int nt = 0; nt < 8; nt++) {
                int col = 8 * (h * 8 + nt) + 2 * cc;
                float b0 = sb[col], b1 = sb[col + 1];
                int row = mb + 16 * mt + r;
                int wrd = 4 * (h * 8 + nt) + cc;
                sH1w[row * SH1S + wrd] =
                    packh2(fmaxf(C1[mt][nt][0] + b0, 0.f), fmaxf(C1[mt][nt][1] + b1, 0.f));
                sH1w[(row + 8) * SH1S + wrd] =
                    packh2(fmaxf(C1[mt][nt][2] + b0, 0.f), fmaxf(C1[mt][nt][3] + b1, 0.f));
            }
    }

    // ---- fc2 + fc3, 4 chunks of N64 (fc3 accumulates over K=256) ----
    float C3[2][8][4];
#pragma unroll
    for (int mt = 0; mt < 2; mt++)
#pragma unroll
        for (int nt = 0; nt < 8; nt++)
#pragma unroll
            for (int q = 0; q < 4; q++) C3[mt][nt][q] = 0.f;

    for (int nc = 0; nc < 4; nc++) {
        __syncthreads();   // fc1 done / prior chunk's B+H2 reads complete
#pragma unroll
        for (int ii = 0; ii < 8; ii++) {
            int i = tid + ii * 256;       // 2048 uint2: W2 K128 x N64 chunk
            int ln = i & 31, ntl = (i >> 5) & 7, kt = i >> 8;
            b2f[i] = g_w2h[(kt * 32 + nc * 8 + ntl) * 32 + ln];
        }
#pragma unroll
        for (int ii = 0; ii < 8; ii++) {
            int i = tid + ii * 256;       // 2048 uint2: W3 K64 x N128 chunk
            int ln = i & 31, nt = (i >> 5) & 15, ktl = i >> 9;
            b3f[i] = g_w3h[((nc * 4 + ktl) * 16 + nt) * 32 + ln];
        }
        __syncthreads();

        // fc2: warp M32 x N32 (h-half of the N64 chunk)
        float C2[2][4][4];
#pragma unroll
        for (int mt = 0; mt < 2; mt++)
#pragma unroll
            for (int nt = 0; nt < 4; nt++)
#pragma unroll
                for (int q = 0; q < 4; q++) C2[mt][nt][q] = 0.f;

#pragma unroll
        for (int kt = 0; kt < 8; kt++) {
            uint32_t a0[4], a1[4];
            ldmatrix_x4(a0, h1la0 + kt * 32);
            ldmatrix_x4(a1, h1la1 + kt * 32);
#pragma unroll
            for (int ntl = 0; ntl < 4; ntl++) {
                uint2 bf = b2f[(kt * 8 + h * 4 + ntl) * 32 + lane];
                mma_f16(C2[0][ntl], a0, bf.x, bf.y);
                mma_f16(C2[1][ntl], a1, bf.x, bf.y);
            }
        }
#pragma unroll
        for (int mt = 0; mt < 2; mt++)
#pragma unroll
            for (int ntl = 0; ntl < 4; ntl++) {
                int colc = 8 * (h * 4 + ntl) + 2 * cc;     // chunk-local col
                float b0 = sb[128 + nc * 64 + colc];
                float b1 = sb[128 + nc * 64 + colc + 1];
                int row = mb + 16 * mt + r;
                int wrd = 4 * (h * 4 + ntl) + cc;
                sH2w[row * SH2S + wrd] =
                    packh2(fmaxf(C2[mt][ntl][0] + b0, 0.f), fmaxf(C2[mt][ntl][1] + b1, 0.f));
                sH2w[(row + 8) * SH2S + wrd] =
                    packh2(fmaxf(C2[mt][ntl][2] + b0, 0.f), fmaxf(C2[mt][ntl][3] + b1, 0.f));
            }
        // pair barrier: partner's H2 half must land before fc3 reads K64
        asm volatile("bar.sync %0, %1;" :: "r"(1 + g), "r"(64) : "memory");

        // fc3: warp M32 x N64 (h-half of N128); K64 chunk
#pragma unroll
        for (int ktl = 0; ktl < 4; ktl++) {
            uint32_t a0[4], a1[4];
            ldmatrix_x4(a0, h2la0 + ktl * 32);
            ldmatrix_x4(a1, h2la1 + ktl * 32);
#pragma unroll
            for (int nt = 0; nt < 8; nt++) {
                uint2 bf = b3f[(ktl * 16 + h * 8 + nt) * 32 + lane];
                mma_f16(C3[0][nt], a0, bf.x, bf.y);
                mma_f16(C3[1][nt], a1, bf.x, bf.y);
            }
        }
    }

    // ---- fc4: pred = relu(C3 + b3) . w4 + b4; cc-shfl + pair smem reduce ----
    float bias4 = sb[640];
#pragma unroll
    for (int mt = 0; mt < 2; mt++) {
        float acc0 = 0.f, acc1 = 0.f;
#pragma unroll
        for (int nt = 0; nt < 8; nt++) {
            int col = 8 * (h * 8 + nt) + 2 * cc;
            float b30 = sb[384 + col], b31 = sb[384 + col + 1];
            float w40 = sb[512 + col], w41 = sb[512 + col + 1];
            acc0 += fmaxf(C3[mt][nt][0] + b30, 0.f) * w40
                  + fmaxf(C3[mt][nt][1] + b31, 0.f) * w41;
            acc1 += fmaxf(C3[mt][nt][2] + b30, 0.f) * w40
                  + fmaxf(C3[mt][nt][3] + b31, 0.f) * w41;
        }
        acc0 += __shfl_xor_sync(0xffffffffu, acc0, 1);
        acc0 += __shfl_xor_sync(0xffffffffu, acc0, 2);
        acc1 += __shfl_xor_sync(0xffffffffu, acc1, 1);
        acc1 += __shfl_xor_sync(0xffffffffu, acc1, 2);
        if (cc == 0) {
            int row = mb + 16 * mt + r;          // block-local row
            spred[row * 2 + h] = acc0;
            spred[(row + 8) * 2 + h] = acc1;
        }
    }
    __syncthreads();
    if (tid < 128) {
        int gidx = m0 + tid;
        float pred = spred[tid * 2] + spred[tid * 2 + 1] + bias4;
        int p = gidx >> 8;
        if ((p >> 5) == (p & 31)) pred = 0.f;    // s == t mask
        g_preds[gidx] = pred;
    }
}

// =======================================================================
// Kernel 3: propagation — warp per row p; block partials to g_part.
// =======================================================================
#define PW 8
__global__ void __launch_bounds__(PW * 32) prop_kernel(const int* __restrict__ edges)
{
    __shared__ float spart[PW][32 * 33];
    __shared__ float srbc[N_NODES];
    __shared__ int sue[N_EDGES], sve[N_EDGES];

    int tid = threadIdx.x, l = tid & 31, w = tid >> 5;
    if (tid < 32) srbc[tid] = 0.f;
    for (int i = tid; i < N_EDGES; i += PW * 32) {
        sue[i] = edges[2 * i];
        sve[i] = edges[2 * i + 1];
    }
    __syncthreads();

    int p = blockIdx.x * PW + w;
    int s = p >> 5;

    int eu[8], ev[8];
    float pr[8];
#pragma unroll
    for (int k = 0; k < 8; k++) { eu[k] = sue[l * 8 + k]; ev[k] = sve[l * 8 + k]; }
    {
        float4 p0 = *(const float4*)&g_preds[p * 256 + l * 8];
        float4 p1 = *(const float4*)&g_preds[p * 256 + l * 8 + 4];
        pr[0] = p0.x; pr[1] = p0.y; pr[2] = p0.z; pr[3] = p0.w;
        pr[4] = p1.x; pr[5] = p1.y; pr[6] = p1.z; pr[7] = p1.w;
    }

    float x = (l == s) ? 1.f : 0.f;
    float racc = 0.f;
    float* part = spart[w];

    for (int step = 0; step < 3; step++) {
#pragma unroll
        for (int j = 0; j < 32; j++) part[l * 33 + j] = 0.f;
        __syncwarp();
#pragma unroll
        for (int k = 0; k < 8; k++) {
            float xv = __shfl_sync(0xffffffffu, x, eu[k]);
            part[l * 33 + ev[k]] += xv * pr[k];
        }
        __syncwarp();
        float xn = 0.f;
#pragma unroll
        for (int i = 0; i < 32; i++) xn += part[i * 33 + l];
        x = xn;
        racc += xn;
        __syncwarp();
    }

    atomicAdd(&srbc[l], racc);
    __syncthreads();
    if (tid < 32) g_part[blockIdx.x * 32 + tid] = srbc[tid];
}

__global__ void norm_kernel(float* __restrict__ out) {
    int l = threadIdx.x;   // 32 lanes
    float v = 0.f;
#pragma unroll 8
    for (int b = 0; b < 128; b++) v += g_part[b * 32 + l];
    float sum = v;
#pragma unroll
    for (int o = 16; o > 0; o >>= 1) sum += __shfl_xor_sync(0xffffffffu, sum, o);
    out[l] = v / sum;
}

// =======================================================================
extern "C" void kernel_launch(void* const* d_in, const int* in_sizes, int n_in,
                              void* d_out, int out_size)
{
    const float* emb  = (const float*)d_in[0];
    const int*   edges= (const int*)  d_in[1];
    const float* w1   = (const float*)d_in[2];
    const float* b1   = (const float*)d_in[3];
    const float* w2   = (const float*)d_in[4];
    const float* b2   = (const float*)d_in[5];
    const float* w3   = (const float*)d_in[6];
    const float* b3   = (const float*)d_in[7];
    const float* fc1w = (const float*)d_in[8];
    const float* fc1b = (const float*)d_in[9];
    const float* fc2w = (const float*)d_in[10];
    const float* fc2b = (const float*)d_in[11];
    const float* fc3w = (const float*)d_in[12];
    const float* fc3b = (const float*)d_in[13];
    const float* fc4w = (const float*)d_in[14];
    const float* fc4b = (const float*)d_in[15];
    float* out = (float*)d_out;

    cudaFuncSetAttribute(fc_mma_kernel, cudaFuncAttributeMaxDynamicSharedMemorySize,
                         FC_SMEM_BYTES);

    prep_weights<<<32, 256>>>(fc1w, fc2w, fc3w);
    prep_tab<<<47, 256>>>(emb, w1);
    conv_kernel<<<PPAIR, 256>>>(emb, edges, w1, b1, w2, b2, w3, b3);
    fc_mma_kernel<<<M_TOT / 128, 256, FC_SMEM_BYTES>>>(fc1b, fc2b, fc3b, fc4w, fc4b);
    prop_kernel<<<PPAIR / PW, PW * 32>>>(edges);
    norm_kernel<<<1, 32>>>(out);
}